// round 6
// baseline (speedup 1.0000x reference)
#include <cuda_runtime.h>
#include <cuda_bf16.h>
#include <cstdint>

#define TOKENS 8192
#define FEAT   4096
#define KSPLIT 4

// device scratch (no allocations allowed)
__device__ __align__(16) float    g_h2p[KSPLIT * TOKENS * 64]; // k-split partials
__device__ __align__(16) uint32_t g_WtHi[64 * 2048];   // Wt[r][n] bf16-hi pairs (n-contig)
__device__ __align__(16) uint32_t g_WtLo[64 * 2048];
__device__ __align__(16) uint32_t g_AqHi[FEAT * 32];   // a_q[m][k] bf16-hi pairs (k-contig)
__device__ __align__(16) uint32_t g_AqLo[FEAT * 32];
__device__ __align__(16) uint32_t g_h2Hi[TOKENS * 32]; // h2[t][r] bf16-hi pairs
__device__ __align__(16) uint32_t g_h2Lo[TOKENS * 32];

// ---------------------------------------------------------------------------
// helpers
// ---------------------------------------------------------------------------
__device__ __forceinline__ void split_pack(float2 v, uint32_t& hi, uint32_t& lo) {
    __nv_bfloat162 h = __floats2bfloat162_rn(v.x, v.y);  // x -> low half
    float2 hf = __bfloat1622float2(h);
    __nv_bfloat162 l = __floats2bfloat162_rn(v.x - hf.x, v.y - hf.y);
    hi = *reinterpret_cast<uint32_t*>(&h);
    lo = *reinterpret_cast<uint32_t*>(&l);
}
__device__ __forceinline__ void mma_bf16(float* c, const uint32_t* a,
                                         const uint32_t* b) {
    asm volatile(
        "mma.sync.aligned.m16n8k16.row.col.f32.bf16.bf16.f32 "
        "{%0,%1,%2,%3}, {%4,%5,%6,%7}, {%8,%9}, {%0,%1,%2,%3};"
        : "+f"(c[0]), "+f"(c[1]), "+f"(c[2]), "+f"(c[3])
        : "r"(a[0]), "r"(a[1]), "r"(a[2]), "r"(a[3]), "r"(b[0]), "r"(b[1]));
}
__device__ __forceinline__ float nvfp4_grid(float av) {
    // mids: 0.25 0.75 1.25 1.75 2.5 3.5 5.0 (ties up)
    float g = (av <  0.25f) ? 0.0f : 0.5f;
    g = (av >= 0.75f) ? 1.0f : g;
    g = (av >= 1.25f) ? 1.5f : g;
    g = (av >= 1.75f) ? 2.0f : g;
    g = (av >= 2.5f)  ? 3.0f : g;
    g = (av >= 3.5f)  ? 4.0f : g;
    g = (av >= 5.0f)  ? 6.0f : g;
    return g;
}

// ---------------------------------------------------------------------------
// kPrep: build Wt hi/lo (Wt[r][n] = b_q[n/64][r] * c_q_t[r][n%64]) and
//        a_q hi/lo pairs. 262144 threads.
// ---------------------------------------------------------------------------
__global__ void __launch_bounds__(256) kPrep(
    const float* __restrict__ b_q, const float* __restrict__ c_q_t,
    const float* __restrict__ a_q)
{
    int p = blockIdx.x * 256 + threadIdx.x;
    if (p < 131072) {                  // Wt pairs: r = p/2048, n-pair = p%2048
        int r  = p >> 11;
        int n0 = (p & 2047) * 2;
        int n1 = n0 + 1;
        float w0 = __ldg(&b_q[(n0 >> 6) * 64 + r]) * __ldg(&c_q_t[r * 64 + (n0 & 63)]);
        float w1 = __ldg(&b_q[(n1 >> 6) * 64 + r]) * __ldg(&c_q_t[r * 64 + (n1 & 63)]);
        uint32_t hi, lo;
        split_pack(make_float2(w0, w1), hi, lo);
        g_WtHi[p] = hi; g_WtLo[p] = lo;
    } else {                           // a_q pairs: m = q/32, k-pair = q%32
        int q = p - 131072;
        float2 v = __ldg(reinterpret_cast<const float2*>(a_q) + q);
        uint32_t hi, lo;
        split_pack(v, hi, lo);
        g_AqHi[q] = hi; g_AqLo[q] = lo;
    }
}

// ---------------------------------------------------------------------------
// k1: fused smooth + NVFP4 quant + HMMA GEMM
//   h2[t][r] = sum_n xq[t][n] * Wt[r][n],  K split 4 ways -> fp32 partials.
// CTA: 128 tokens x 64 r, 8 warps (16 tok each). Quant in registers:
// MMA k16 step == quant block 16; amax via shfl over the lane quad.
// ---------------------------------------------------------------------------
__global__ void __launch_bounds__(256) k1_quant_mma(
    const float* __restrict__ x, const float* __restrict__ smooth)
{
    __shared__ float ssm[1024];

    const int t    = threadIdx.x;
    const int wid  = t >> 5, lane = t & 31;
    const int gid  = lane >> 2, tg = lane & 3;
    const int ksb  = blockIdx.x;
    const int t0   = blockIdx.y * 128;
    const int nb   = ksb * 1024;

    reinterpret_cast<float4*>(ssm)[t] =
        __ldg(reinterpret_cast<const float4*>(smooth + nb) + t);
    __syncthreads();

    const int row0 = t0 + wid * 16 + gid;
    const float* xr0 = x + (size_t)row0 * FEAT;
    const float* xr1 = xr0 + (size_t)8 * FEAT;

    float acc[8][4];
#pragma unroll
    for (int ni = 0; ni < 8; ni++)
#pragma unroll
        for (int c = 0; c < 4; c++) acc[ni][c] = 0.0f;

#pragma unroll 4
    for (int ks = 0; ks < 64; ks++) {
        const int kl = ks * 16 + tg * 2;
        const int kg = nb + kl;

        // ---- load + smooth (4 float2 per thread) ----
        float2 x00 = __ldg(reinterpret_cast<const float2*>(xr0 + kg));
        float2 x02 = __ldg(reinterpret_cast<const float2*>(xr0 + kg + 8));
        float2 x10 = __ldg(reinterpret_cast<const float2*>(xr1 + kg));
        float2 x12 = __ldg(reinterpret_cast<const float2*>(xr1 + kg + 8));
        float2 s0 = *reinterpret_cast<const float2*>(&ssm[kl]);
        float2 s2 = *reinterpret_cast<const float2*>(&ssm[kl + 8]);
        float y00x = x00.x * s0.x, y00y = x00.y * s0.y;
        float y02x = x02.x * s2.x, y02y = x02.y * s2.y;
        float y10x = x10.x * s0.x, y10y = x10.y * s0.y;
        float y12x = x12.x * s2.x, y12y = x12.y * s2.y;

        // ---- per-16-block amax via lane-quad shuffle ----
        float m0 = fmaxf(fmaxf(fabsf(y00x), fabsf(y00y)),
                         fmaxf(fabsf(y02x), fabsf(y02y)));
        float m1 = fmaxf(fmaxf(fabsf(y10x), fabsf(y10y)),
                         fmaxf(fabsf(y12x), fabsf(y12y)));
        m0 = fmaxf(m0, __shfl_xor_sync(0xffffffffu, m0, 1));
        m0 = fmaxf(m0, __shfl_xor_sync(0xffffffffu, m0, 2));
        m1 = fmaxf(m1, __shfl_xor_sync(0xffffffffu, m1, 1));
        m1 = fmaxf(m1, __shfl_xor_sync(0xffffffffu, m1, 2));
        float sc0 = fmaxf(m0 * (1.0f / 6.0f), 1e-8f);
        float sc1 = fmaxf(m1 * (1.0f / 6.0f), 1e-8f);
        float iv0 = 1.0f / sc0, iv1 = 1.0f / sc1;

        // ---- quantize + hi/lo split -> A fragments ----
        float q00x = copysignf(nvfp4_grid(fabsf(y00x) * iv0) * sc0, y00x);
        float q00y = copysignf(nvfp4_grid(fabsf(y00y) * iv0) * sc0, y00y);
        float q02x = copysignf(nvfp4_grid(fabsf(y02x) * iv0) * sc0, y02x);
        float q02y = copysignf(nvfp4_grid(fabsf(y02y) * iv0) * sc0, y02y);
        float q10x = copysignf(nvfp4_grid(fabsf(y10x) * iv1) * sc1, y10x);
        float q10y = copysignf(nvfp4_grid(fabsf(y10y) * iv1) * sc1, y10y);
        float q12x = copysignf(nvfp4_grid(fabsf(y12x) * iv1) * sc1, y12x);
        float q12y = copysignf(nvfp4_grid(fabsf(y12y) * iv1) * sc1, y12y);

        uint32_t ah[4], al[4];
        split_pack(make_float2(q00x, q00y), ah[0], al[0]);  // (row0, k)
        split_pack(make_float2(q10x, q10y), ah[1], al[1]);  // (row0+8, k)
        split_pack(make_float2(q02x, q02y), ah[2], al[2]);  // (row0, k+8)
        split_pack(make_float2(q12x, q12y), ah[3], al[3]);  // (row0+8, k+8)

        // ---- B fragments (pre-split Wt) + MMA ----
        const int kb2 = (nb >> 1) + ks * 8 + tg;
#pragma unroll
        for (int ni = 0; ni < 8; ni++) {
            const int col = ni * 8 + gid;
            uint32_t bh[2], bl[2];
            bh[0] = __ldg(&g_WtHi[col * 2048 + kb2]);
            bh[1] = __ldg(&g_WtHi[col * 2048 + kb2 + 4]);
            bl[0] = __ldg(&g_WtLo[col * 2048 + kb2]);
            bl[1] = __ldg(&g_WtLo[col * 2048 + kb2 + 4]);
            mma_bf16(acc[ni], ah, bh);
            mma_bf16(acc[ni], al, bh);
            mma_bf16(acc[ni], ah, bl);
        }
    }

    // ---- store fp32 partials ----
    float* dst = g_h2p + (size_t)ksb * TOKENS * 64;
#pragma unroll
    for (int ni = 0; ni < 8; ni++) {
        const int col = ni * 8 + tg * 2;
        *reinterpret_cast<float2*>(&dst[(size_t)row0 * 64 + col]) =
            make_float2(acc[ni][0], acc[ni][1]);
        *reinterpret_cast<float2*>(&dst[(size_t)(row0 + 8) * 64 + col]) =
            make_float2(acc[ni][2], acc[ni][3]);
    }
}

// ---------------------------------------------------------------------------
// kR: h2 = sum of 4 partials, emitted as pre-split bf16 hi/lo pairs.
// ---------------------------------------------------------------------------
__global__ void __launch_bounds__(256) kR_reduce() {
    int p = blockIdx.x * 256 + threadIdx.x;   // pair index, 262144 total
    const float2* s = reinterpret_cast<const float2*>(g_h2p);
    float2 a = s[p];
    float2 b = s[p + 262144];
    float2 c = s[p + 524288];
    float2 d = s[p + 786432];
    float2 v = make_float2((a.x + b.x) + (c.x + d.x),
                           (a.y + b.y) + (c.y + d.y));
    uint32_t hi, lo;
    split_pack(v, hi, lo);
    g_h2Hi[p] = hi; g_h2Lo[p] = lo;
}

// ---------------------------------------------------------------------------
// k2: out[t][m] = sum_k h2[t][k] * a_q[m][k] + bias[m]
// Pure-load HMMA: all operands pre-split bf16. CTA 128 tok x 128 m,
// 8 warps 4(M)x2(N), warp tile 32 tok x 64 m, K=64 in 4 steps.
// ---------------------------------------------------------------------------
__global__ void __launch_bounds__(256) k2_expand(
    const float* __restrict__ bias,
    float* __restrict__ out)
{
    const int t    = threadIdx.x;
    const int wid  = t >> 5, lane = t & 31;
    const int gid  = lane >> 2, tg = lane & 3;
    const int wm   = wid & 3, wn = wid >> 2;
    const int m0   = blockIdx.x * 128 + wn * 64;
    const int t0   = blockIdx.y * 128 + wm * 32;

    float acc[2][8][4];
#pragma unroll
    for (int mi = 0; mi < 2; mi++)
#pragma unroll
        for (int ni = 0; ni < 8; ni++)
#pragma unroll
            for (int c = 0; c < 4; c++) acc[mi][ni][c] = 0.0f;

#pragma unroll
    for (int ks = 0; ks < 4; ks++) {
        const int ko = ks * 8 + tg;

        uint32_t ahi[2][4], alo[2][4];
#pragma unroll
        for (int mi = 0; mi < 2; mi++) {
            const int rp = (t0 + mi * 16 + gid) * 32 + ko;
            ahi[mi][0] = __ldg(&g_h2Hi[rp]);
            ahi[mi][1] = __ldg(&g_h2Hi[rp + 8 * 32]);
            ahi[mi][2] = __ldg(&g_h2Hi[rp + 4]);
            ahi[mi][3] = __ldg(&g_h2Hi[rp + 8 * 32 + 4]);
            alo[mi][0] = __ldg(&g_h2Lo[rp]);
            alo[mi][1] = __ldg(&g_h2Lo[rp + 8 * 32]);
            alo[mi][2] = __ldg(&g_h2Lo[rp + 4]);
            alo[mi][3] = __ldg(&g_h2Lo[rp + 8 * 32 + 4]);
        }

#pragma unroll
        for (int ni = 0; ni < 8; ni++) {
            const int cp = (m0 + ni * 8 + gid) * 32 + ko;
            uint32_t bh[2], bl[2];
            bh[0] = __ldg(&g_AqHi[cp]);
            bh[1] = __ldg(&g_AqHi[cp + 4]);
            bl[0] = __ldg(&g_AqLo[cp]);
            bl[1] = __ldg(&g_AqLo[cp + 4]);
#pragma unroll
            for (int mi = 0; mi < 2; mi++) {
                mma_bf16(acc[mi][ni], ahi[mi], bh);
                mma_bf16(acc[mi][ni], alo[mi], bh);
                mma_bf16(acc[mi][ni], ahi[mi], bl);
            }
        }
    }

    // epilogue: + bias, float2 stores
#pragma unroll
    for (int ni = 0; ni < 8; ni++) {
        const int col = m0 + ni * 8 + tg * 2;
        float2 bv = __ldg(reinterpret_cast<const float2*>(bias + col));
#pragma unroll
        for (int mi = 0; mi < 2; mi++) {
            const int row = t0 + mi * 16 + gid;
            float2 o0 = make_float2(acc[mi][ni][0] + bv.x, acc[mi][ni][1] + bv.y);
            float2 o1 = make_float2(acc[mi][ni][2] + bv.x, acc[mi][ni][3] + bv.y);
            *reinterpret_cast<float2*>(out + (size_t)row * FEAT + col)       = o0;
            *reinterpret_cast<float2*>(out + (size_t)(row + 8) * FEAT + col) = o1;
        }
    }
}

extern "C" void kernel_launch(void* const* d_in, const int* in_sizes, int n_in,
                              void* d_out, int out_size) {
    const float* x      = (const float*)d_in[0];
    const float* smooth = (const float*)d_in[1];
    const float* a_q    = (const float*)d_in[2];
    const float* b_q    = (const float*)d_in[3];
    const float* c_q_t  = (const float*)d_in[4];
    const float* bias   = (const float*)d_in[5];
    float* out          = (float*)d_out;

    kPrep<<<1024, 256>>>(b_q, c_q_t, a_q);
    k1_quant_mma<<<dim3(KSPLIT, 64), 256>>>(x, smooth);
    kR_reduce<<<1024, 256>>>();
    k2_expand<<<dim3(32, 64), 256>>>(bias, out);
}

// round 7
// speedup vs baseline: 1.7343x; 1.7343x over previous
#include <cuda_runtime.h>
#include <cuda_bf16.h>
#include <cstdint>

#define TOKENS 8192
#define FEAT   4096
#define KSPLIT 4

// device scratch (no allocations allowed)
__device__ __align__(16) float g_h2p[KSPLIT * TOKENS * 64]; // k-split partials (8 MB)
__device__ __align__(16) uint4 g_WtF[65536];   // Wt frag-order (hi01,hi89,lo01,lo89) 1 MB
__device__ __align__(16) uint4 g_AqF[65536];   // a_q frag-order 1 MB
__device__ __align__(16) uint4 g_h2FH[65536];  // h2 A-frag hi (1 MB)
__device__ __align__(16) uint4 g_h2FL[65536];  // h2 A-frag lo (1 MB)

// ---------------------------------------------------------------------------
// helpers
// ---------------------------------------------------------------------------
__device__ __forceinline__ void split_pack(float2 v, uint32_t& hi, uint32_t& lo) {
    __nv_bfloat162 h = __floats2bfloat162_rn(v.x, v.y);  // x -> low half
    float2 hf = __bfloat1622float2(h);
    __nv_bfloat162 l = __floats2bfloat162_rn(v.x - hf.x, v.y - hf.y);
    hi = *reinterpret_cast<uint32_t*>(&h);
    lo = *reinterpret_cast<uint32_t*>(&l);
}
__device__ __forceinline__ void mma_bf16(float* c, const uint32_t* a,
                                         uint32_t b0, uint32_t b1) {
    asm volatile(
        "mma.sync.aligned.m16n8k16.row.col.f32.bf16.bf16.f32 "
        "{%0,%1,%2,%3}, {%4,%5,%6,%7}, {%8,%9}, {%0,%1,%2,%3};"
        : "+f"(c[0]), "+f"(c[1]), "+f"(c[2]), "+f"(c[3])
        : "r"(a[0]), "r"(a[1]), "r"(a[2]), "r"(a[3]), "r"(b0), "r"(b1));
}
__device__ __forceinline__ float nvfp4_grid(float av) {
    float g = (av <  0.25f) ? 0.0f : 0.5f;
    g = (av >= 0.75f) ? 1.0f : g;
    g = (av >= 1.25f) ? 1.5f : g;
    g = (av >= 1.75f) ? 2.0f : g;
    g = (av >= 2.5f)  ? 3.0f : g;
    g = (av >= 3.5f)  ? 4.0f : g;
    g = (av >= 5.0f)  ? 6.0f : g;
    return g;
}

// ---------------------------------------------------------------------------
// kPrep: build fragment-ordered Wt (b_q folded into c_q_t) and a_q splits.
//  Wt[r][n] = b_q[n/64][r] * c_q_t[r][n%64]
//  Wt frag p (p<65536): f=p>>5 -> gks=f>>3, ni=f&7; lane: gid=col, tg=k-pair
//  Aq frag q: f=q>>5 -> c8=f>>2, ks=f&3
// ---------------------------------------------------------------------------
__global__ void __launch_bounds__(256) kPrep(
    const float* __restrict__ b_q, const float* __restrict__ c_q_t,
    const float* __restrict__ a_q)
{
    int p = blockIdx.x * 256 + threadIdx.x;
    int lane = p & 31, tg = lane & 3, gid = (lane >> 2) & 7;
    if (p < 65536) {
        int f = p >> 5;
        int ni = f & 7, gks = f >> 3;
        int r  = ni * 8 + gid;
        int n0 = gks * 16 + tg * 2;
        float w00 = __ldg(&b_q[((n0)     >> 6) * 64 + r]) * __ldg(&c_q_t[r * 64 + ((n0)     & 63)]);
        float w01 = __ldg(&b_q[((n0 + 1) >> 6) * 64 + r]) * __ldg(&c_q_t[r * 64 + ((n0 + 1) & 63)]);
        float w80 = __ldg(&b_q[((n0 + 8) >> 6) * 64 + r]) * __ldg(&c_q_t[r * 64 + ((n0 + 8) & 63)]);
        float w81 = __ldg(&b_q[((n0 + 9) >> 6) * 64 + r]) * __ldg(&c_q_t[r * 64 + ((n0 + 9) & 63)]);
        uint32_t h0, l0, h1, l1;
        split_pack(make_float2(w00, w01), h0, l0);
        split_pack(make_float2(w80, w81), h1, l1);
        uint4 o; o.x = h0; o.y = h1; o.z = l0; o.w = l1;
        g_WtF[p] = o;
    } else {
        int q = p - 65536;
        int f = q >> 5;
        int ks = f & 3, c8 = f >> 2;
        int c  = c8 * 8 + gid;
        int k0 = ks * 16 + tg * 2;
        const float* ar = a_q + (size_t)c * 64;
        float2 v0 = __ldg(reinterpret_cast<const float2*>(ar + k0));
        float2 v8 = __ldg(reinterpret_cast<const float2*>(ar + k0 + 8));
        uint32_t h0, l0, h1, l1;
        split_pack(v0, h0, l0);
        split_pack(v8, h1, l1);
        uint4 o; o.x = h0; o.y = h1; o.z = l0; o.w = l1;
        g_AqF[q] = o;
    }
}

// ---------------------------------------------------------------------------
// k1: fused smooth + NVFP4 quant + HMMA GEMM, K split 4 ways.
// CTA 128 tok x 64 r, 8 warps (16 tok each). B frags: one uint4 LDG each.
// ---------------------------------------------------------------------------
__global__ void __launch_bounds__(256) k1_quant_mma(
    const float* __restrict__ x, const float* __restrict__ smooth)
{
    __shared__ float ssm[1024];

    const int t    = threadIdx.x;
    const int wid  = t >> 5, lane = t & 31;
    const int gid  = lane >> 2, tg = lane & 3;
    const int ksb  = blockIdx.x;
    const int t0   = blockIdx.y * 128;
    const int nb   = ksb * 1024;

    reinterpret_cast<float4*>(ssm)[t] =
        __ldg(reinterpret_cast<const float4*>(smooth + nb) + t);
    __syncthreads();

    const int row0 = t0 + wid * 16 + gid;
    const float* xr0 = x + (size_t)row0 * FEAT;
    const float* xr1 = xr0 + (size_t)8 * FEAT;

    float acc[8][4];
#pragma unroll
    for (int ni = 0; ni < 8; ni++)
#pragma unroll
        for (int c = 0; c < 4; c++) acc[ni][c] = 0.0f;

#pragma unroll 4
    for (int ks = 0; ks < 64; ks++) {
        const int kl = ks * 16 + tg * 2;
        const int kg = nb + kl;

        // ---- load + smooth ----
        float2 x00 = __ldg(reinterpret_cast<const float2*>(xr0 + kg));
        float2 x02 = __ldg(reinterpret_cast<const float2*>(xr0 + kg + 8));
        float2 x10 = __ldg(reinterpret_cast<const float2*>(xr1 + kg));
        float2 x12 = __ldg(reinterpret_cast<const float2*>(xr1 + kg + 8));
        float2 s0 = *reinterpret_cast<const float2*>(&ssm[kl]);
        float2 s2 = *reinterpret_cast<const float2*>(&ssm[kl + 8]);
        float y00x = x00.x * s0.x, y00y = x00.y * s0.y;
        float y02x = x02.x * s2.x, y02y = x02.y * s2.y;
        float y10x = x10.x * s0.x, y10y = x10.y * s0.y;
        float y12x = x12.x * s2.x, y12y = x12.y * s2.y;

        // ---- per-16-block amax via lane-quad shuffle ----
        float m0 = fmaxf(fmaxf(fabsf(y00x), fabsf(y00y)),
                         fmaxf(fabsf(y02x), fabsf(y02y)));
        float m1 = fmaxf(fmaxf(fabsf(y10x), fabsf(y10y)),
                         fmaxf(fabsf(y12x), fabsf(y12y)));
        m0 = fmaxf(m0, __shfl_xor_sync(0xffffffffu, m0, 1));
        m0 = fmaxf(m0, __shfl_xor_sync(0xffffffffu, m0, 2));
        m1 = fmaxf(m1, __shfl_xor_sync(0xffffffffu, m1, 1));
        m1 = fmaxf(m1, __shfl_xor_sync(0xffffffffu, m1, 2));
        float sc0 = fmaxf(m0 * (1.0f / 6.0f), 1e-8f);
        float sc1 = fmaxf(m1 * (1.0f / 6.0f), 1e-8f);
        float iv0 = 1.0f / sc0, iv1 = 1.0f / sc1;

        // ---- quantize + hi/lo split -> A fragments ----
        float q00x = copysignf(nvfp4_grid(fabsf(y00x) * iv0) * sc0, y00x);
        float q00y = copysignf(nvfp4_grid(fabsf(y00y) * iv0) * sc0, y00y);
        float q02x = copysignf(nvfp4_grid(fabsf(y02x) * iv0) * sc0, y02x);
        float q02y = copysignf(nvfp4_grid(fabsf(y02y) * iv0) * sc0, y02y);
        float q10x = copysignf(nvfp4_grid(fabsf(y10x) * iv1) * sc1, y10x);
        float q10y = copysignf(nvfp4_grid(fabsf(y10y) * iv1) * sc1, y10y);
        float q12x = copysignf(nvfp4_grid(fabsf(y12x) * iv1) * sc1, y12x);
        float q12y = copysignf(nvfp4_grid(fabsf(y12y) * iv1) * sc1, y12y);

        uint32_t ah[4], al[4];
        split_pack(make_float2(q00x, q00y), ah[0], al[0]);  // (row0,   k)
        split_pack(make_float2(q10x, q10y), ah[1], al[1]);  // (row0+8, k)
        split_pack(make_float2(q02x, q02y), ah[2], al[2]);  // (row0,   k+8)
        split_pack(make_float2(q12x, q12y), ah[3], al[3]);  // (row0+8, k+8)

        // ---- B fragments: one uint4 LDG each + 3 MMAs ----
        const int fb = ((ksb * 64 + ks) * 8) * 32 + lane;
#pragma unroll
        for (int ni = 0; ni < 8; ni++) {
            uint4 wf = __ldg(&g_WtF[fb + ni * 32]);
            mma_bf16(acc[ni], ah, wf.x, wf.y);
            mma_bf16(acc[ni], al, wf.x, wf.y);
            mma_bf16(acc[ni], ah, wf.z, wf.w);
        }
    }

    // ---- store fp32 partials ----
    float* dst = g_h2p + (size_t)ksb * TOKENS * 64;
#pragma unroll
    for (int ni = 0; ni < 8; ni++) {
        const int col = ni * 8 + tg * 2;
        *reinterpret_cast<float2*>(&dst[(size_t)row0 * 64 + col]) =
            make_float2(acc[ni][0], acc[ni][1]);
        *reinterpret_cast<float2*>(&dst[(size_t)(row0 + 8) * 64 + col]) =
            make_float2(acc[ni][2], acc[ni][3]);
    }
}

// ---------------------------------------------------------------------------
// kR: h2 = sum of 4 partials -> frag-ordered hi/lo uint4 arrays.
// idx: lane(32) | ks(4) | rt16(512)
// ---------------------------------------------------------------------------
__global__ void __launch_bounds__(256) kR_reduce() {
    int idx = blockIdx.x * 256 + threadIdx.x;   // 65536 total
    int lane = idx & 31, tg = lane & 3, gid = (lane >> 2) & 7;
    int ks = (idx >> 5) & 3;
    int rt16 = idx >> 7;
    int row = rt16 * 16 + gid;
    int k0  = ks * 16 + tg * 2;

    float2 v[4];
#pragma unroll
    for (int j = 0; j < 4; j++) v[j] = make_float2(0.f, 0.f);
#pragma unroll
    for (int part = 0; part < KSPLIT; part++) {
        const float* base = g_h2p + (size_t)part * TOKENS * 64;
        const float2 a0 = *reinterpret_cast<const float2*>(base + (size_t)row * 64 + k0);
        const float2 a1 = *reinterpret_cast<const float2*>(base + (size_t)(row + 8) * 64 + k0);
        const float2 a2 = *reinterpret_cast<const float2*>(base + (size_t)row * 64 + k0 + 8);
        const float2 a3 = *reinterpret_cast<const float2*>(base + (size_t)(row + 8) * 64 + k0 + 8);
        v[0].x += a0.x; v[0].y += a0.y;
        v[1].x += a1.x; v[1].y += a1.y;
        v[2].x += a2.x; v[2].y += a2.y;
        v[3].x += a3.x; v[3].y += a3.y;
    }
    uint4 oh, ol;
    split_pack(v[0], oh.x, ol.x);
    split_pack(v[1], oh.y, ol.y);
    split_pack(v[2], oh.z, ol.z);
    split_pack(v[3], oh.w, ol.w);
    g_h2FH[idx] = oh;
    g_h2FL[idx] = ol;
}

// ---------------------------------------------------------------------------
// k2: out[t][m] = sum_k h2[t][k] * a_q[m][k] + bias[m]
// All operands frag-ordered uint4. CTA 128 tok x 128 m, warps 4(M)x2(N).
// ---------------------------------------------------------------------------
__global__ void __launch_bounds__(256) k2_expand(
    const float* __restrict__ bias,
    float* __restrict__ out)
{
    const int t    = threadIdx.x;
    const int wid  = t >> 5, lane = t & 31;
    const int gid  = lane >> 2, tg = lane & 3;
    const int wm   = wid & 3, wn = wid >> 2;
    const int m0   = blockIdx.x * 128 + wn * 64;
    const int t0   = blockIdx.y * 128 + wm * 32;
    const int rtb  = blockIdx.y * 8 + wm * 2;    // 16-row group base
    const int c8b  = blockIdx.x * 16 + wn * 8;   // 8-col group base

    float acc[2][8][4];
#pragma unroll
    for (int mi = 0; mi < 2; mi++)
#pragma unroll
        for (int ni = 0; ni < 8; ni++)
#pragma unroll
            for (int c = 0; c < 4; c++) acc[mi][ni][c] = 0.0f;

#pragma unroll
    for (int ks = 0; ks < 4; ks++) {
        uint4 ah[2], al[2];
#pragma unroll
        for (int mi = 0; mi < 2; mi++) {
            int ia = ((rtb + mi) * 4 + ks) * 32 + lane;
            ah[mi] = __ldg(&g_h2FH[ia]);
            al[mi] = __ldg(&g_h2FL[ia]);
        }
#pragma unroll
        for (int ni = 0; ni < 8; ni++) {
            int ib = ((c8b + ni) * 4 + ks) * 32 + lane;
            uint4 wf = __ldg(&g_AqF[ib]);
#pragma unroll
            for (int mi = 0; mi < 2; mi++) {
                mma_bf16(acc[mi][ni], reinterpret_cast<uint32_t*>(&ah[mi]), wf.x, wf.y);
                mma_bf16(acc[mi][ni], reinterpret_cast<uint32_t*>(&al[mi]), wf.x, wf.y);
                mma_bf16(acc[mi][ni], reinterpret_cast<uint32_t*>(&ah[mi]), wf.z, wf.w);
            }
        }
    }

    // epilogue: + bias, float2 stores
#pragma unroll
    for (int ni = 0; ni < 8; ni++) {
        const int col = m0 + ni * 8 + tg * 2;
        float2 bv = __ldg(reinterpret_cast<const float2*>(bias + col));
#pragma unroll
        for (int mi = 0; mi < 2; mi++) {
            const int row = t0 + mi * 16 + gid;
            float2 o0 = make_float2(acc[mi][ni][0] + bv.x, acc[mi][ni][1] + bv.y);
            float2 o1 = make_float2(acc[mi][ni][2] + bv.x, acc[mi][ni][3] + bv.y);
            *reinterpret_cast<float2*>(out + (size_t)row * FEAT + col)       = o0;
            *reinterpret_cast<float2*>(out + (size_t)(row + 8) * FEAT + col) = o1;
        }
    }
}

extern "C" void kernel_launch(void* const* d_in, const int* in_sizes, int n_in,
                              void* d_out, int out_size) {
    const float* x      = (const float*)d_in[0];
    const float* smooth = (const float*)d_in[1];
    const float* a_q    = (const float*)d_in[2];
    const float* b_q    = (const float*)d_in[3];
    const float* c_q_t  = (const float*)d_in[4];
    const float* bias   = (const float*)d_in[5];
    float* out          = (float*)d_out;

    kPrep<<<512, 256>>>(b_q, c_q_t, a_q);
    k1_quant_mma<<<dim3(KSPLIT, 64), 256>>>(x, smooth);
    kR_reduce<<<256, 256>>>();
    k2_expand<<<dim3(32, 64), 256>>>(bias, out);
}

// round 8
// speedup vs baseline: 2.3120x; 1.3331x over previous
#include <cuda_runtime.h>
#include <cuda_bf16.h>
#include <cstdint>

#define TOKENS 8192
#define FEAT   4096
#define KSPLIT 4

// device scratch (no allocations allowed)
__device__ __align__(16) float g_h2p[KSPLIT * TOKENS * 64]; // k-split partials (8 MB)
__device__ __align__(16) uint4 g_WtF[65536];   // Wt frag-order (hi01,hi89,lo01,lo89) 1 MB
__device__ __align__(16) uint4 g_AqF[65536];   // a_q frag-order 1 MB
__device__ __align__(16) uint4 g_h2FH[65536];  // h2 A-frag hi (1 MB)
__device__ __align__(16) uint4 g_h2FL[65536];  // h2 A-frag lo (1 MB)

// ---------------------------------------------------------------------------
// helpers
// ---------------------------------------------------------------------------
__device__ __forceinline__ void split_pack(float2 v, uint32_t& hi, uint32_t& lo) {
    __nv_bfloat162 h = __floats2bfloat162_rn(v.x, v.y);  // x -> low half
    float2 hf = __bfloat1622float2(h);
    __nv_bfloat162 l = __floats2bfloat162_rn(v.x - hf.x, v.y - hf.y);
    hi = *reinterpret_cast<uint32_t*>(&h);
    lo = *reinterpret_cast<uint32_t*>(&l);
}
__device__ __forceinline__ uint32_t pack_bf16x2(float a, float b) {
    __nv_bfloat162 h = __floats2bfloat162_rn(a, b);
    return *reinterpret_cast<uint32_t*>(&h);
}
// acc-accumulating MMA
__device__ __forceinline__ void mma_bf16(float* c, const uint32_t* a,
                                         uint32_t b0, uint32_t b1) {
    asm volatile(
        "mma.sync.aligned.m16n8k16.row.col.f32.bf16.bf16.f32 "
        "{%0,%1,%2,%3}, {%4,%5,%6,%7}, {%8,%9}, {%0,%1,%2,%3};"
        : "+f"(c[0]), "+f"(c[1]), "+f"(c[2]), "+f"(c[3])
        : "r"(a[0]), "r"(a[1]), "r"(a[2]), "r"(a[3]), "r"(b0), "r"(b1));
}
// zero-seeded MMA: d = A*B (c operands are constant zero)
__device__ __forceinline__ void mma_bf16_z(float* d, const uint32_t* a,
                                           uint32_t b0, uint32_t b1) {
    asm volatile(
        "mma.sync.aligned.m16n8k16.row.col.f32.bf16.bf16.f32 "
        "{%0,%1,%2,%3}, {%4,%5,%6,%7}, {%8,%9}, {%10,%11,%12,%13};"
        : "=f"(d[0]), "=f"(d[1]), "=f"(d[2]), "=f"(d[3])
        : "r"(a[0]), "r"(a[1]), "r"(a[2]), "r"(a[3]), "r"(b0), "r"(b1),
          "f"(0.0f), "f"(0.0f), "f"(0.0f), "f"(0.0f));
}
__device__ __forceinline__ float nvfp4_grid(float av) {
    float g = (av <  0.25f) ? 0.0f : 0.5f;
    g = (av >= 0.75f) ? 1.0f : g;
    g = (av >= 1.25f) ? 1.5f : g;
    g = (av >= 1.75f) ? 2.0f : g;
    g = (av >= 2.5f)  ? 3.0f : g;
    g = (av >= 3.5f)  ? 4.0f : g;
    g = (av >= 5.0f)  ? 6.0f : g;
    return g;
}

// ---------------------------------------------------------------------------
// kPrep: build fragment-ordered Wt (b_q folded into c_q_t) and a_q splits.
// ---------------------------------------------------------------------------
__global__ void __launch_bounds__(256) kPrep(
    const float* __restrict__ b_q, const float* __restrict__ c_q_t,
    const float* __restrict__ a_q)
{
    int p = blockIdx.x * 256 + threadIdx.x;
    int lane = p & 31, tg = lane & 3, gid = (lane >> 2) & 7;
    if (p < 65536) {
        int f = p >> 5;
        int ni = f & 7, gks = f >> 3;
        int r  = ni * 8 + gid;
        int n0 = gks * 16 + tg * 2;
        float w00 = __ldg(&b_q[((n0)     >> 6) * 64 + r]) * __ldg(&c_q_t[r * 64 + ((n0)     & 63)]);
        float w01 = __ldg(&b_q[((n0 + 1) >> 6) * 64 + r]) * __ldg(&c_q_t[r * 64 + ((n0 + 1) & 63)]);
        float w80 = __ldg(&b_q[((n0 + 8) >> 6) * 64 + r]) * __ldg(&c_q_t[r * 64 + ((n0 + 8) & 63)]);
        float w81 = __ldg(&b_q[((n0 + 9) >> 6) * 64 + r]) * __ldg(&c_q_t[r * 64 + ((n0 + 9) & 63)]);
        uint32_t h0, l0, h1, l1;
        split_pack(make_float2(w00, w01), h0, l0);
        split_pack(make_float2(w80, w81), h1, l1);
        uint4 o; o.x = h0; o.y = h1; o.z = l0; o.w = l1;
        g_WtF[p] = o;
    } else {
        int q = p - 65536;
        int f = q >> 5;
        int ks = f & 3, c8 = f >> 2;
        int c  = c8 * 8 + gid;
        int k0 = ks * 16 + tg * 2;
        const float* ar = a_q + (size_t)c * 64;
        float2 v0 = __ldg(reinterpret_cast<const float2*>(ar + k0));
        float2 v8 = __ldg(reinterpret_cast<const float2*>(ar + k0 + 8));
        uint32_t h0, l0, h1, l1;
        split_pack(v0, h0, l0);
        split_pack(v8, h1, l1);
        uint4 o; o.x = h0; o.y = h1; o.z = l0; o.w = l1;
        g_AqF[q] = o;
    }
}

// ---------------------------------------------------------------------------
// k1: fused smooth + NVFP4 quant + HMMA GEMM, K split 4 ways.
// A fragments = exact bf16 grid values q; block scale folded into acc after
// a zero-seeded MMA pair (P = q*Wh + q*Wl; acc += sc_row * P).
// ---------------------------------------------------------------------------
__global__ void __launch_bounds__(256, 2) k1_quant_mma(
    const float* __restrict__ x, const float* __restrict__ smooth)
{
    __shared__ float ssm[1024];

    const int t    = threadIdx.x;
    const int wid  = t >> 5, lane = t & 31;
    const int gid  = lane >> 2, tg = lane & 3;
    const int ksb  = blockIdx.x;
    const int t0   = blockIdx.y * 128;
    const int nb   = ksb * 1024;

    reinterpret_cast<float4*>(ssm)[t] =
        __ldg(reinterpret_cast<const float4*>(smooth + nb) + t);
    __syncthreads();

    const int row0 = t0 + wid * 16 + gid;
    const float* xr0 = x + (size_t)row0 * FEAT;
    const float* xr1 = xr0 + (size_t)8 * FEAT;

    float acc[8][4];
#pragma unroll
    for (int ni = 0; ni < 8; ni++)
#pragma unroll
        for (int c = 0; c < 4; c++) acc[ni][c] = 0.0f;

#pragma unroll 4
    for (int ks = 0; ks < 64; ks++) {
        const int kl = ks * 16 + tg * 2;
        const int kg = nb + kl;

        // ---- load + smooth ----
        float2 x00 = __ldg(reinterpret_cast<const float2*>(xr0 + kg));
        float2 x02 = __ldg(reinterpret_cast<const float2*>(xr0 + kg + 8));
        float2 x10 = __ldg(reinterpret_cast<const float2*>(xr1 + kg));
        float2 x12 = __ldg(reinterpret_cast<const float2*>(xr1 + kg + 8));
        float2 s0 = *reinterpret_cast<const float2*>(&ssm[kl]);
        float2 s2 = *reinterpret_cast<const float2*>(&ssm[kl + 8]);
        float y00x = x00.x * s0.x, y00y = x00.y * s0.y;
        float y02x = x02.x * s2.x, y02y = x02.y * s2.y;
        float y10x = x10.x * s0.x, y10y = x10.y * s0.y;
        float y12x = x12.x * s2.x, y12y = x12.y * s2.y;

        // ---- per-16-block amax via lane-quad shuffle ----
        float m0 = fmaxf(fmaxf(fabsf(y00x), fabsf(y00y)),
                         fmaxf(fabsf(y02x), fabsf(y02y)));
        float m1 = fmaxf(fmaxf(fabsf(y10x), fabsf(y10y)),
                         fmaxf(fabsf(y12x), fabsf(y12y)));
        m0 = fmaxf(m0, __shfl_xor_sync(0xffffffffu, m0, 1));
        m0 = fmaxf(m0, __shfl_xor_sync(0xffffffffu, m0, 2));
        m1 = fmaxf(m1, __shfl_xor_sync(0xffffffffu, m1, 1));
        m1 = fmaxf(m1, __shfl_xor_sync(0xffffffffu, m1, 2));
        float sc0 = fmaxf(m0 * (1.0f / 6.0f), 1e-8f);
        float sc1 = fmaxf(m1 * (1.0f / 6.0f), 1e-8f);
        float iv0 = 1.0f / sc0, iv1 = 1.0f / sc1;

        // ---- quantize to exact-bf16 grid values (no dequant multiply) ----
        float q00x = copysignf(nvfp4_grid(fabsf(y00x) * iv0), y00x);
        float q00y = copysignf(nvfp4_grid(fabsf(y00y) * iv0), y00y);
        float q02x = copysignf(nvfp4_grid(fabsf(y02x) * iv0), y02x);
        float q02y = copysignf(nvfp4_grid(fabsf(y02y) * iv0), y02y);
        float q10x = copysignf(nvfp4_grid(fabsf(y10x) * iv1), y10x);
        float q10y = copysignf(nvfp4_grid(fabsf(y10y) * iv1), y10y);
        float q12x = copysignf(nvfp4_grid(fabsf(y12x) * iv1), y12x);
        float q12y = copysignf(nvfp4_grid(fabsf(y12y) * iv1), y12y);

        uint32_t aq[4];
        aq[0] = pack_bf16x2(q00x, q00y);  // (row0,   k)
        aq[1] = pack_bf16x2(q10x, q10y);  // (row0+8, k)
        aq[2] = pack_bf16x2(q02x, q02y);  // (row0,   k+8)
        aq[3] = pack_bf16x2(q12x, q12y);  // (row0+8, k+8)

        // ---- B fragments: one uint4 LDG; P = q*Wh + q*Wl; fold scales ----
        const int fb = ((ksb * 64 + ks) * 8) * 32 + lane;
#pragma unroll
        for (int ni = 0; ni < 8; ni++) {
            uint4 wf = __ldg(&g_WtF[fb + ni * 32]);
            float p[4];
            mma_bf16_z(p, aq, wf.x, wf.y);
            mma_bf16(p, aq, wf.z, wf.w);
            acc[ni][0] += sc0 * p[0];
            acc[ni][1] += sc0 * p[1];
            acc[ni][2] += sc1 * p[2];
            acc[ni][3] += sc1 * p[3];
        }
    }

    // ---- store fp32 partials ----
    float* dst = g_h2p + (size_t)ksb * TOKENS * 64;
#pragma unroll
    for (int ni = 0; ni < 8; ni++) {
        const int col = ni * 8 + tg * 2;
        *reinterpret_cast<float2*>(&dst[(size_t)row0 * 64 + col]) =
            make_float2(acc[ni][0], acc[ni][1]);
        *reinterpret_cast<float2*>(&dst[(size_t)(row0 + 8) * 64 + col]) =
            make_float2(acc[ni][2], acc[ni][3]);
    }
}

// ---------------------------------------------------------------------------
// kR: h2 = sum of 4 partials -> frag-ordered hi/lo uint4 arrays.
// ---------------------------------------------------------------------------
__global__ void __launch_bounds__(256) kR_reduce() {
    int idx = blockIdx.x * 256 + threadIdx.x;   // 65536 total
    int lane = idx & 31, tg = lane & 3, gid = (lane >> 2) & 7;
    int ks = (idx >> 5) & 3;
    int rt16 = idx >> 7;
    int row = rt16 * 16 + gid;
    int k0  = ks * 16 + tg * 2;

    float2 v[4];
#pragma unroll
    for (int j = 0; j < 4; j++) v[j] = make_float2(0.f, 0.f);
#pragma unroll
    for (int part = 0; part < KSPLIT; part++) {
        const float* base = g_h2p + (size_t)part * TOKENS * 64;
        const float2 a0 = *reinterpret_cast<const float2*>(base + (size_t)row * 64 + k0);
        const float2 a1 = *reinterpret_cast<const float2*>(base + (size_t)(row + 8) * 64 + k0);
        const float2 a2 = *reinterpret_cast<const float2*>(base + (size_t)row * 64 + k0 + 8);
        const float2 a3 = *reinterpret_cast<const float2*>(base + (size_t)(row + 8) * 64 + k0 + 8);
        v[0].x += a0.x; v[0].y += a0.y;
        v[1].x += a1.x; v[1].y += a1.y;
        v[2].x += a2.x; v[2].y += a2.y;
        v[3].x += a3.x; v[3].y += a3.y;
    }
    uint4 oh, ol;
    split_pack(v[0], oh.x, ol.x);
    split_pack(v[1], oh.y, ol.y);
    split_pack(v[2], oh.z, ol.z);
    split_pack(v[3], oh.w, ol.w);
    g_h2FH[idx] = oh;
    g_h2FL[idx] = ol;
}

// ---------------------------------------------------------------------------
// k2: out[t][m] = sum_k h2[t][k] * a_q[m][k] + bias[m]
// All operands frag-ordered uint4. CTA 128 tok x 128 m, warps 4(M)x2(N).
// ---------------------------------------------------------------------------
__global__ void __launch_bounds__(256, 2) k2_expand(
    const float* __restrict__ bias,
    float* __restrict__ out)
{
    const int t    = threadIdx.x;
    const int wid  = t >> 5, lane = t & 31;
    const int gid  = lane >> 2, tg = lane & 3;
    const int wm   = wid & 3, wn = wid >> 2;
    const int m0   = blockIdx.x * 128 + wn * 64;
    const int t0   = blockIdx.y * 128 + wm * 32;
    const int rtb  = blockIdx.y * 8 + wm * 2;    // 16-row group base
    const int c8b  = blockIdx.x * 16 + wn * 8;   // 8-col group base

    float acc[2][8][4];
#pragma unroll
    for (int mi = 0; mi < 2; mi++)
#pragma unroll
        for (int ni = 0; ni < 8; ni++)
#pragma unroll
            for (int c = 0; c < 4; c++) acc[mi][ni][c] = 0.0f;

#pragma unroll
    for (int ks = 0; ks < 4; ks++) {
        uint4 ah[2], al[2];
#pragma unroll
        for (int mi = 0; mi < 2; mi++) {
            int ia = ((rtb + mi) * 4 + ks) * 32 + lane;
            ah[mi] = __ldg(&g_h2FH[ia]);
            al[mi] = __ldg(&g_h2FL[ia]);
        }
#pragma unroll
        for (int ni = 0; ni < 8; ni++) {
            int ib = ((c8b + ni) * 4 + ks) * 32 + lane;
            uint4 wf = __ldg(&g_AqF[ib]);
#pragma unroll
            for (int mi = 0; mi < 2; mi++) {
                mma_bf16(acc[mi][ni], reinterpret_cast<uint32_t*>(&ah[mi]), wf.x, wf.y);
                mma_bf16(acc[mi][ni], reinterpret_cast<uint32_t*>(&al[mi]), wf.x, wf.y);
                mma_bf16(acc[mi][ni], reinterpret_cast<uint32_t*>(&ah[mi]), wf.z, wf.w);
            }
        }
    }

    // epilogue: + bias, float2 stores
#pragma unroll
    for (int ni = 0; ni < 8; ni++) {
        const int col = m0 + ni * 8 + tg * 2;
        float2 bv = __ldg(reinterpret_cast<const float2*>(bias + col));
#pragma unroll
        for (int mi = 0; mi < 2; mi++) {
            const int row = t0 + mi * 16 + gid;
            float2 o0 = make_float2(acc[mi][ni][0] + bv.x, acc[mi][ni][1] + bv.y);
            float2 o1 = make_float2(acc[mi][ni][2] + bv.x, acc[mi][ni][3] + bv.y);
            *reinterpret_cast<float2*>(out + (size_t)row * FEAT + col)       = o0;
            *reinterpret_cast<float2*>(out + (size_t)(row + 8) * FEAT + col) = o1;
        }
    }
}

extern "C" void kernel_launch(void* const* d_in, const int* in_sizes, int n_in,
                              void* d_out, int out_size) {
    const float* x      = (const float*)d_in[0];
    const float* smooth = (const float*)d_in[1];
    const float* a_q    = (const float*)d_in[2];
    const float* b_q    = (const float*)d_in[3];
    const float* c_q_t  = (const float*)d_in[4];
    const float* bias   = (const float*)d_in[5];
    float* out          = (float*)d_out;

    kPrep<<<512, 256>>>(b_q, c_q_t, a_q);
    k1_quant_mma<<<dim3(KSPLIT, 64), 256>>>(x, smooth);
    kR_reduce<<<256, 256>>>();
    k2_expand<<<dim3(32, 64), 256>>>(bias, out);
}

// round 9
// speedup vs baseline: 2.3998x; 1.0380x over previous
#include <cuda_runtime.h>
#include <cuda_bf16.h>
#include <cstdint>

#define TOKENS 8192
#define FEAT   4096
#define KSPLIT 4

// device scratch (no allocations allowed)
__device__ __align__(16) float g_h2p[KSPLIT * TOKENS * 64]; // k-split partials (8 MB)
__device__ __align__(16) uint4 g_WtF[65536];   // Wt frag-order (hi01,hi89,lo01,lo89) 1 MB
__device__ __align__(16) uint4 g_AqF[65536];   // a_q frag-order 1 MB
__device__ __align__(16) uint4 g_h2FH[65536];  // h2 A-frag hi (1 MB)
__device__ __align__(16) uint4 g_h2FL[65536];  // h2 A-frag lo (1 MB)

// ---------------------------------------------------------------------------
// helpers
// ---------------------------------------------------------------------------
__device__ __forceinline__ void split_pack(float2 v, uint32_t& hi, uint32_t& lo) {
    __nv_bfloat162 h = __floats2bfloat162_rn(v.x, v.y);  // x -> low half
    float2 hf = __bfloat1622float2(h);
    __nv_bfloat162 l = __floats2bfloat162_rn(v.x - hf.x, v.y - hf.y);
    hi = *reinterpret_cast<uint32_t*>(&h);
    lo = *reinterpret_cast<uint32_t*>(&l);
}
__device__ __forceinline__ uint32_t pack_bf16x2(float a, float b) {
    __nv_bfloat162 h = __floats2bfloat162_rn(a, b);
    return *reinterpret_cast<uint32_t*>(&h);
}
// acc-accumulating MMA
__device__ __forceinline__ void mma_bf16(float* c, const uint32_t* a,
                                         uint32_t b0, uint32_t b1) {
    asm volatile(
        "mma.sync.aligned.m16n8k16.row.col.f32.bf16.bf16.f32 "
        "{%0,%1,%2,%3}, {%4,%5,%6,%7}, {%8,%9}, {%0,%1,%2,%3};"
        : "+f"(c[0]), "+f"(c[1]), "+f"(c[2]), "+f"(c[3])
        : "r"(a[0]), "r"(a[1]), "r"(a[2]), "r"(a[3]), "r"(b0), "r"(b1));
}
// zero-seeded MMA: d = A*B
__device__ __forceinline__ void mma_bf16_z(float* d, const uint32_t* a,
                                           uint32_t b0, uint32_t b1) {
    asm volatile(
        "mma.sync.aligned.m16n8k16.row.col.f32.bf16.bf16.f32 "
        "{%0,%1,%2,%3}, {%4,%5,%6,%7}, {%8,%9}, {%10,%11,%12,%13};"
        : "=f"(d[0]), "=f"(d[1]), "=f"(d[2]), "=f"(d[3])
        : "r"(a[0]), "r"(a[1]), "r"(a[2]), "r"(a[3]), "r"(b0), "r"(b1),
          "f"(0.0f), "f"(0.0f), "f"(0.0f), "f"(0.0f));
}
__device__ __forceinline__ float nvfp4_grid(float av) {
    float g = (av <  0.25f) ? 0.0f : 0.5f;
    g = (av >= 0.75f) ? 1.0f : g;
    g = (av >= 1.25f) ? 1.5f : g;
    g = (av >= 1.75f) ? 2.0f : g;
    g = (av >= 2.5f)  ? 3.0f : g;
    g = (av >= 3.5f)  ? 4.0f : g;
    g = (av >= 5.0f)  ? 6.0f : g;
    return g;
}

// ---------------------------------------------------------------------------
// kPrep: build fragment-ordered Wt (b_q folded into c_q_t) and a_q splits.
// ---------------------------------------------------------------------------
__global__ void __launch_bounds__(256) kPrep(
    const float* __restrict__ b_q, const float* __restrict__ c_q_t,
    const float* __restrict__ a_q)
{
    int p = blockIdx.x * 256 + threadIdx.x;
    int lane = p & 31, tg = lane & 3, gid = (lane >> 2) & 7;
    if (p < 65536) {
        int f = p >> 5;
        int ni = f & 7, gks = f >> 3;
        int r  = ni * 8 + gid;
        int n0 = gks * 16 + tg * 2;
        float w00 = __ldg(&b_q[((n0)     >> 6) * 64 + r]) * __ldg(&c_q_t[r * 64 + ((n0)     & 63)]);
        float w01 = __ldg(&b_q[((n0 + 1) >> 6) * 64 + r]) * __ldg(&c_q_t[r * 64 + ((n0 + 1) & 63)]);
        float w80 = __ldg(&b_q[((n0 + 8) >> 6) * 64 + r]) * __ldg(&c_q_t[r * 64 + ((n0 + 8) & 63)]);
        float w81 = __ldg(&b_q[((n0 + 9) >> 6) * 64 + r]) * __ldg(&c_q_t[r * 64 + ((n0 + 9) & 63)]);
        uint32_t h0, l0, h1, l1;
        split_pack(make_float2(w00, w01), h0, l0);
        split_pack(make_float2(w80, w81), h1, l1);
        uint4 o; o.x = h0; o.y = h1; o.z = l0; o.w = l1;
        g_WtF[p] = o;
    } else {
        int q = p - 65536;
        int f = q >> 5;
        int ks = f & 3, c8 = f >> 2;
        int c  = c8 * 8 + gid;
        int k0 = ks * 16 + tg * 2;
        const float* ar = a_q + (size_t)c * 64;
        float2 v0 = __ldg(reinterpret_cast<const float2*>(ar + k0));
        float2 v8 = __ldg(reinterpret_cast<const float2*>(ar + k0 + 8));
        uint32_t h0, l0, h1, l1;
        split_pack(v0, h0, l0);
        split_pack(v8, h1, l1);
        uint4 o; o.x = h0; o.y = h1; o.z = l0; o.w = l1;
        g_AqF[q] = o;
    }
}

// ---------------------------------------------------------------------------
// k1: fused smooth + NVFP4 quant + HMMA GEMM, K split 4 ways.
// ---------------------------------------------------------------------------
__global__ void __launch_bounds__(256, 2) k1_quant_mma(
    const float* __restrict__ x, const float* __restrict__ smooth)
{
    __shared__ float ssm[1024];

    const int t    = threadIdx.x;
    const int wid  = t >> 5, lane = t & 31;
    const int gid  = lane >> 2, tg = lane & 3;
    const int ksb  = blockIdx.x;
    const int t0   = blockIdx.y * 128;
    const int nb   = ksb * 1024;

    reinterpret_cast<float4*>(ssm)[t] =
        __ldg(reinterpret_cast<const float4*>(smooth + nb) + t);
    __syncthreads();

    const int row0 = t0 + wid * 16 + gid;
    const float* xr0 = x + (size_t)row0 * FEAT;
    const float* xr1 = xr0 + (size_t)8 * FEAT;

    float acc[8][4];
#pragma unroll
    for (int ni = 0; ni < 8; ni++)
#pragma unroll
        for (int c = 0; c < 4; c++) acc[ni][c] = 0.0f;

#pragma unroll 4
    for (int ks = 0; ks < 64; ks++) {
        const int kl = ks * 16 + tg * 2;
        const int kg = nb + kl;

        // ---- load + smooth ----
        float2 x00 = __ldg(reinterpret_cast<const float2*>(xr0 + kg));
        float2 x02 = __ldg(reinterpret_cast<const float2*>(xr0 + kg + 8));
        float2 x10 = __ldg(reinterpret_cast<const float2*>(xr1 + kg));
        float2 x12 = __ldg(reinterpret_cast<const float2*>(xr1 + kg + 8));
        float2 s0 = *reinterpret_cast<const float2*>(&ssm[kl]);
        float2 s2 = *reinterpret_cast<const float2*>(&ssm[kl + 8]);
        float y00x = x00.x * s0.x, y00y = x00.y * s0.y;
        float y02x = x02.x * s2.x, y02y = x02.y * s2.y;
        float y10x = x10.x * s0.x, y10y = x10.y * s0.y;
        float y12x = x12.x * s2.x, y12y = x12.y * s2.y;

        // ---- per-16-block amax via lane-quad shuffle ----
        float m0 = fmaxf(fmaxf(fabsf(y00x), fabsf(y00y)),
                         fmaxf(fabsf(y02x), fabsf(y02y)));
        float m1 = fmaxf(fmaxf(fabsf(y10x), fabsf(y10y)),
                         fmaxf(fabsf(y12x), fabsf(y12y)));
        m0 = fmaxf(m0, __shfl_xor_sync(0xffffffffu, m0, 1));
        m0 = fmaxf(m0, __shfl_xor_sync(0xffffffffu, m0, 2));
        m1 = fmaxf(m1, __shfl_xor_sync(0xffffffffu, m1, 1));
        m1 = fmaxf(m1, __shfl_xor_sync(0xffffffffu, m1, 2));
        float sc0 = fmaxf(m0 * (1.0f / 6.0f), 1e-8f);
        float sc1 = fmaxf(m1 * (1.0f / 6.0f), 1e-8f);
        float iv0 = 1.0f / sc0, iv1 = 1.0f / sc1;

        // ---- quantize to exact-bf16 grid values ----
        float q00x = copysignf(nvfp4_grid(fabsf(y00x) * iv0), y00x);
        float q00y = copysignf(nvfp4_grid(fabsf(y00y) * iv0), y00y);
        float q02x = copysignf(nvfp4_grid(fabsf(y02x) * iv0), y02x);
        float q02y = copysignf(nvfp4_grid(fabsf(y02y) * iv0), y02y);
        float q10x = copysignf(nvfp4_grid(fabsf(y10x) * iv1), y10x);
        float q10y = copysignf(nvfp4_grid(fabsf(y10y) * iv1), y10y);
        float q12x = copysignf(nvfp4_grid(fabsf(y12x) * iv1), y12x);
        float q12y = copysignf(nvfp4_grid(fabsf(y12y) * iv1), y12y);

        uint32_t aq[4];
        aq[0] = pack_bf16x2(q00x, q00y);
        aq[1] = pack_bf16x2(q10x, q10y);
        aq[2] = pack_bf16x2(q02x, q02y);
        aq[3] = pack_bf16x2(q12x, q12y);

        // ---- B fragments + zero-seeded MMA pair + scale fold ----
        const int fb = ((ksb * 64 + ks) * 8) * 32 + lane;
#pragma unroll
        for (int ni = 0; ni < 8; ni++) {
            uint4 wf = __ldg(&g_WtF[fb + ni * 32]);
            float p[4];
            mma_bf16_z(p, aq, wf.x, wf.y);
            mma_bf16(p, aq, wf.z, wf.w);
            acc[ni][0] += sc0 * p[0];
            acc[ni][1] += sc0 * p[1];
            acc[ni][2] += sc1 * p[2];
            acc[ni][3] += sc1 * p[3];
        }
    }

    // ---- store fp32 partials ----
    float* dst = g_h2p + (size_t)ksb * TOKENS * 64;
#pragma unroll
    for (int ni = 0; ni < 8; ni++) {
        const int col = ni * 8 + tg * 2;
        *reinterpret_cast<float2*>(&dst[(size_t)row0 * 64 + col]) =
            make_float2(acc[ni][0], acc[ni][1]);
        *reinterpret_cast<float2*>(&dst[(size_t)(row0 + 8) * 64 + col]) =
            make_float2(acc[ni][2], acc[ni][3]);
    }
}

// ---------------------------------------------------------------------------
// kR: h2 = sum of 4 partials -> frag-ordered hi/lo uint4 arrays.
// ---------------------------------------------------------------------------
__global__ void __launch_bounds__(256) kR_reduce() {
    int idx = blockIdx.x * 256 + threadIdx.x;   // 65536 total
    int lane = idx & 31, tg = lane & 3, gid = (lane >> 2) & 7;
    int ks = (idx >> 5) & 3;
    int rt16 = idx >> 7;
    int row = rt16 * 16 + gid;
    int k0  = ks * 16 + tg * 2;

    float2 v[4];
#pragma unroll
    for (int j = 0; j < 4; j++) v[j] = make_float2(0.f, 0.f);
#pragma unroll
    for (int part = 0; part < KSPLIT; part++) {
        const float* base = g_h2p + (size_t)part * TOKENS * 64;
        const float2 a0 = *reinterpret_cast<const float2*>(base + (size_t)row * 64 + k0);
        const float2 a1 = *reinterpret_cast<const float2*>(base + (size_t)(row + 8) * 64 + k0);
        const float2 a2 = *reinterpret_cast<const float2*>(base + (size_t)row * 64 + k0 + 8);
        const float2 a3 = *reinterpret_cast<const float2*>(base + (size_t)(row + 8) * 64 + k0 + 8);
        v[0].x += a0.x; v[0].y += a0.y;
        v[1].x += a1.x; v[1].y += a1.y;
        v[2].x += a2.x; v[2].y += a2.y;
        v[3].x += a3.x; v[3].y += a3.y;
    }
    uint4 oh, ol;
    split_pack(v[0], oh.x, ol.x);
    split_pack(v[1], oh.y, ol.y);
    split_pack(v[2], oh.z, ol.z);
    split_pack(v[3], oh.w, ol.w);
    g_h2FH[idx] = oh;
    g_h2FL[idx] = ol;
}

// ---------------------------------------------------------------------------
// k2: out[t][m] = sum_k h2[t][k] * a_q[m][k] + bias[m]
// Warp tile 32tok x 32m (acc = 32 regs -> room to hoist next-ks frags).
// CTA 128 tok x 64 m, warps 4(M) x 2(N). Grid (64, 64).
// ---------------------------------------------------------------------------
__global__ void __launch_bounds__(256, 2) k2_expand(
    const float* __restrict__ bias,
    float* __restrict__ out)
{
    const int t    = threadIdx.x;
    const int wid  = t >> 5, lane = t & 31;
    const int gid  = lane >> 2, tg = lane & 3;
    const int wm   = wid & 3, wn = wid >> 2;
    const int m0   = blockIdx.x * 64 + wn * 32;
    const int t0   = blockIdx.y * 128 + wm * 32;
    const int rtb  = blockIdx.y * 8 + wm * 2;    // 16-row group base
    const int c8b  = blockIdx.x * 8 + wn * 4;    // 8-col group base

    float acc[2][4][4];
#pragma unroll
    for (int mi = 0; mi < 2; mi++)
#pragma unroll
        for (int ni = 0; ni < 4; ni++)
#pragma unroll
            for (int c = 0; c < 4; c++) acc[mi][ni][c] = 0.0f;

#pragma unroll
    for (int ks = 0; ks < 4; ks++) {
        uint4 ah[2], al[2], wf[4];
#pragma unroll
        for (int mi = 0; mi < 2; mi++) {
            int ia = ((rtb + mi) * 4 + ks) * 32 + lane;
            ah[mi] = __ldg(&g_h2FH[ia]);
            al[mi] = __ldg(&g_h2FL[ia]);
        }
#pragma unroll
        for (int ni = 0; ni < 4; ni++) {
            int ib = ((c8b + ni) * 4 + ks) * 32 + lane;
            wf[ni] = __ldg(&g_AqF[ib]);
        }
#pragma unroll
        for (int ni = 0; ni < 4; ni++) {
#pragma unroll
            for (int mi = 0; mi < 2; mi++) {
                mma_bf16(acc[mi][ni], reinterpret_cast<uint32_t*>(&ah[mi]), wf[ni].x, wf[ni].y);
                mma_bf16(acc[mi][ni], reinterpret_cast<uint32_t*>(&al[mi]), wf[ni].x, wf[ni].y);
                mma_bf16(acc[mi][ni], reinterpret_cast<uint32_t*>(&ah[mi]), wf[ni].z, wf[ni].w);
            }
        }
    }

    // epilogue: + bias, float2 stores
#pragma unroll
    for (int ni = 0; ni < 4; ni++) {
        const int col = m0 + ni * 8 + tg * 2;
        float2 bv = __ldg(reinterpret_cast<const float2*>(bias + col));
#pragma unroll
        for (int mi = 0; mi < 2; mi++) {
            const int row = t0 + mi * 16 + gid;
            float2 o0 = make_float2(acc[mi][ni][0] + bv.x, acc[mi][ni][1] + bv.y);
            float2 o1 = make_float2(acc[mi][ni][2] + bv.x, acc[mi][ni][3] + bv.y);
            *reinterpret_cast<float2*>(out + (size_t)row * FEAT + col)       = o0;
            *reinterpret_cast<float2*>(out + (size_t)(row + 8) * FEAT + col) = o1;
        }
    }
}

extern "C" void kernel_launch(void* const* d_in, const int* in_sizes, int n_in,
                              void* d_out, int out_size) {
    const float* x      = (const float*)d_in[0];
    const float* smooth = (const float*)d_in[1];
    const float* a_q    = (const float*)d_in[2];
    const float* b_q    = (const float*)d_in[3];
    const float* c_q_t  = (const float*)d_in[4];
    const float* bias   = (const float*)d_in[5];
    float* out          = (float*)d_out;

    kPrep<<<512, 256>>>(b_q, c_q_t, a_q);
    k1_quant_mma<<<dim3(KSPLIT, 64), 256>>>(x, smooth);
    kR_reduce<<<256, 256>>>();
    k2_expand<<<dim3(64, 64), 256>>>(bias, out);
}

// round 11
// speedup vs baseline: 2.6096x; 1.0874x over previous
#include <cuda_runtime.h>
#include <cuda_bf16.h>
#include <cstdint>

#define TOKENS 8192
#define FEAT   4096
#define KSPLIT 4

// device scratch (no allocations allowed)
__device__ __align__(16) float g_h2p[KSPLIT * TOKENS * 64]; // k-split partials (8 MB)
__device__ __align__(16) uint4 g_WtF[65536];   // Wt frag-order (hi01,hi89,lo01,lo89) 1 MB
__device__ __align__(16) uint4 g_AqF[65536];   // a_q frag-order 1 MB
__device__ __align__(16) uint4 g_h2FH[65536];  // h2 A-frag hi (1 MB)
__device__ __align__(16) uint4 g_h2FL[65536];  // h2 A-frag lo (1 MB)

// ---------------------------------------------------------------------------
// helpers
// ---------------------------------------------------------------------------
__device__ __forceinline__ void split_pack(float2 v, uint32_t& hi, uint32_t& lo) {
    __nv_bfloat162 h = __floats2bfloat162_rn(v.x, v.y);  // x -> low half
    float2 hf = __bfloat1622float2(h);
    __nv_bfloat162 l = __floats2bfloat162_rn(v.x - hf.x, v.y - hf.y);
    hi = *reinterpret_cast<uint32_t*>(&h);
    lo = *reinterpret_cast<uint32_t*>(&l);
}
__device__ __forceinline__ uint32_t pack_bf16x2(float a, float b) {
    __nv_bfloat162 h = __floats2bfloat162_rn(a, b);
    return *reinterpret_cast<uint32_t*>(&h);
}
// packed f32x2 helpers
__device__ __forceinline__ unsigned long long ffma2(unsigned long long a,
                                                    unsigned long long b,
                                                    unsigned long long c) {
    unsigned long long d;
    asm("fma.rn.f32x2 %0, %1, %2, %3;" : "=l"(d) : "l"(a), "l"(b), "l"(c));
    return d;
}
__device__ __forceinline__ unsigned long long dup2(float x) {
    unsigned long long r;
    asm("mov.b64 %0, {%1, %1};" : "=l"(r) : "f"(x));
    return r;
}
__device__ __forceinline__ unsigned long long pack2f(float a, float b) {
    unsigned long long r;
    asm("mov.b64 %0, {%1, %2};" : "=l"(r) : "f"(a), "f"(b));
    return r;
}
__device__ __forceinline__ float2 unpack2(unsigned long long v) {
    float lo, hi;
    asm("mov.b64 {%0, %1}, %2;" : "=f"(lo), "=f"(hi) : "l"(v));
    return make_float2(lo, hi);
}
// acc-accumulating MMA
__device__ __forceinline__ void mma_bf16(float* c, const uint32_t* a,
                                         uint32_t b0, uint32_t b1) {
    asm volatile(
        "mma.sync.aligned.m16n8k16.row.col.f32.bf16.bf16.f32 "
        "{%0,%1,%2,%3}, {%4,%5,%6,%7}, {%8,%9}, {%0,%1,%2,%3};"
        : "+f"(c[0]), "+f"(c[1]), "+f"(c[2]), "+f"(c[3])
        : "r"(a[0]), "r"(a[1]), "r"(a[2]), "r"(a[3]), "r"(b0), "r"(b1));
}
// zero-seeded MMA: d = A*B
__device__ __forceinline__ void mma_bf16_z(float* d, const uint32_t* a,
                                           uint32_t b0, uint32_t b1) {
    asm volatile(
        "mma.sync.aligned.m16n8k16.row.col.f32.bf16.bf16.f32 "
        "{%0,%1,%2,%3}, {%4,%5,%6,%7}, {%8,%9}, {%10,%11,%12,%13};"
        : "=f"(d[0]), "=f"(d[1]), "=f"(d[2]), "=f"(d[3])
        : "r"(a[0]), "r"(a[1]), "r"(a[2]), "r"(a[3]), "r"(b0), "r"(b1),
          "f"(0.0f), "f"(0.0f), "f"(0.0f), "f"(0.0f));
}
// E2M1 grid round (half-up, matches searchsorted 'right').
// Bit trick valid ONLY for av >= 1 (E2M1's [0.5,1) binade is subnormal:
// the grid has no 0.75). Sub-1 region handled by explicit selects.
__device__ __forceinline__ float nvfp4_round(float av) {
    uint32_t ur = (__float_as_uint(av) + 0x00200000u) & 0xFFC00000u;
    float qa = fminf(__uint_as_float(ur), 6.0f);
    float qs = (av < 0.25f) ? 0.0f : 0.5f;
    qs = (av >= 0.75f) ? 1.0f : qs;
    return (av < 1.0f) ? qs : qa;
}

// ---------------------------------------------------------------------------
// kPrep: build fragment-ordered Wt (b_q folded into c_q_t) and a_q splits.
// ---------------------------------------------------------------------------
__global__ void __launch_bounds__(256) kPrep(
    const float* __restrict__ b_q, const float* __restrict__ c_q_t,
    const float* __restrict__ a_q)
{
    int p = blockIdx.x * 256 + threadIdx.x;
    int lane = p & 31, tg = lane & 3, gid = (lane >> 2) & 7;
    if (p < 65536) {
        int f = p >> 5;
        int ni = f & 7, gks = f >> 3;
        int r  = ni * 8 + gid;
        int n0 = gks * 16 + tg * 2;
        float w00 = __ldg(&b_q[((n0)     >> 6) * 64 + r]) * __ldg(&c_q_t[r * 64 + ((n0)     & 63)]);
        float w01 = __ldg(&b_q[((n0 + 1) >> 6) * 64 + r]) * __ldg(&c_q_t[r * 64 + ((n0 + 1) & 63)]);
        float w80 = __ldg(&b_q[((n0 + 8) >> 6) * 64 + r]) * __ldg(&c_q_t[r * 64 + ((n0 + 8) & 63)]);
        float w81 = __ldg(&b_q[((n0 + 9) >> 6) * 64 + r]) * __ldg(&c_q_t[r * 64 + ((n0 + 9) & 63)]);
        uint32_t h0, l0, h1, l1;
        split_pack(make_float2(w00, w01), h0, l0);
        split_pack(make_float2(w80, w81), h1, l1);
        uint4 o; o.x = h0; o.y = h1; o.z = l0; o.w = l1;
        g_WtF[p] = o;
    } else {
        int q = p - 65536;
        int f = q >> 5;
        int ks = f & 3, c8 = f >> 2;
        int c  = c8 * 8 + gid;
        int k0 = ks * 16 + tg * 2;
        const float* ar = a_q + (size_t)c * 64;
        float2 v0 = __ldg(reinterpret_cast<const float2*>(ar + k0));
        float2 v8 = __ldg(reinterpret_cast<const float2*>(ar + k0 + 8));
        uint32_t h0, l0, h1, l1;
        split_pack(v0, h0, l0);
        split_pack(v8, h1, l1);
        uint4 o; o.x = h0; o.y = h1; o.z = l0; o.w = l1;
        g_AqF[q] = o;
    }
}

// ---------------------------------------------------------------------------
// k1: fused smooth + NVFP4 quant + HMMA GEMM, K split 4 ways.
// Bit-trick grid round (fixed sub-1 binade) + f32x2 scale fold.
// ---------------------------------------------------------------------------
__global__ void __launch_bounds__(256, 2) k1_quant_mma(
    const float* __restrict__ x, const float* __restrict__ smooth)
{
    __shared__ float ssm[1024];

    const int t    = threadIdx.x;
    const int wid  = t >> 5, lane = t & 31;
    const int gid  = lane >> 2, tg = lane & 3;
    const int ksb  = blockIdx.x;
    const int t0   = blockIdx.y * 128;
    const int nb   = ksb * 1024;

    reinterpret_cast<float4*>(ssm)[t] =
        __ldg(reinterpret_cast<const float4*>(smooth + nb) + t);
    __syncthreads();

    const int row0 = t0 + wid * 16 + gid;
    const float* xr0 = x + (size_t)row0 * FEAT;
    const float* xr1 = xr0 + (size_t)8 * FEAT;

    unsigned long long acc2[8][2];
#pragma unroll
    for (int ni = 0; ni < 8; ni++) { acc2[ni][0] = 0ull; acc2[ni][1] = 0ull; }

#pragma unroll 4
    for (int ks = 0; ks < 64; ks++) {
        const int kl = ks * 16 + tg * 2;
        const int kg = nb + kl;

        // ---- load + smooth ----
        float2 x00 = __ldg(reinterpret_cast<const float2*>(xr0 + kg));
        float2 x02 = __ldg(reinterpret_cast<const float2*>(xr0 + kg + 8));
        float2 x10 = __ldg(reinterpret_cast<const float2*>(xr1 + kg));
        float2 x12 = __ldg(reinterpret_cast<const float2*>(xr1 + kg + 8));
        float2 s0 = *reinterpret_cast<const float2*>(&ssm[kl]);
        float2 s2 = *reinterpret_cast<const float2*>(&ssm[kl + 8]);
        float y00x = x00.x * s0.x, y00y = x00.y * s0.y;
        float y02x = x02.x * s2.x, y02y = x02.y * s2.y;
        float y10x = x10.x * s0.x, y10y = x10.y * s0.y;
        float y12x = x12.x * s2.x, y12y = x12.y * s2.y;

        // ---- per-16-block amax via lane-quad shuffle ----
        float m0 = fmaxf(fmaxf(fabsf(y00x), fabsf(y00y)),
                         fmaxf(fabsf(y02x), fabsf(y02y)));
        float m1 = fmaxf(fmaxf(fabsf(y10x), fabsf(y10y)),
                         fmaxf(fabsf(y12x), fabsf(y12y)));
        m0 = fmaxf(m0, __shfl_xor_sync(0xffffffffu, m0, 1));
        m0 = fmaxf(m0, __shfl_xor_sync(0xffffffffu, m0, 2));
        m1 = fmaxf(m1, __shfl_xor_sync(0xffffffffu, m1, 1));
        m1 = fmaxf(m1, __shfl_xor_sync(0xffffffffu, m1, 2));
        float sc0 = fmaxf(m0 * (1.0f / 6.0f), 1e-8f);
        float sc1 = fmaxf(m1 * (1.0f / 6.0f), 1e-8f);
        float iv0 = 1.0f / sc0, iv1 = 1.0f / sc1;

        // ---- quantize to exact-bf16 grid values ----
        float q00x = copysignf(nvfp4_round(fabsf(y00x) * iv0), y00x);
        float q00y = copysignf(nvfp4_round(fabsf(y00y) * iv0), y00y);
        float q02x = copysignf(nvfp4_round(fabsf(y02x) * iv0), y02x);
        float q02y = copysignf(nvfp4_round(fabsf(y02y) * iv0), y02y);
        float q10x = copysignf(nvfp4_round(fabsf(y10x) * iv1), y10x);
        float q10y = copysignf(nvfp4_round(fabsf(y10y) * iv1), y10y);
        float q12x = copysignf(nvfp4_round(fabsf(y12x) * iv1), y12x);
        float q12y = copysignf(nvfp4_round(fabsf(y12y) * iv1), y12y);

        uint32_t aq[4];
        aq[0] = pack_bf16x2(q00x, q00y);
        aq[1] = pack_bf16x2(q10x, q10y);
        aq[2] = pack_bf16x2(q02x, q02y);
        aq[3] = pack_bf16x2(q12x, q12y);

        // ---- B fragments + zero-seeded MMA pair + packed scale fold ----
        const unsigned long long s0d = dup2(sc0);
        const unsigned long long s1d = dup2(sc1);
        const int fb = ((ksb * 64 + ks) * 8) * 32 + lane;
#pragma unroll
        for (int ni = 0; ni < 8; ni++) {
            uint4 wf = __ldg(&g_WtF[fb + ni * 32]);
            float p[4];
            mma_bf16_z(p, aq, wf.x, wf.y);
            mma_bf16(p, aq, wf.z, wf.w);
            acc2[ni][0] = ffma2(s0d, pack2f(p[0], p[1]), acc2[ni][0]);
            acc2[ni][1] = ffma2(s1d, pack2f(p[2], p[3]), acc2[ni][1]);
        }
    }

    // ---- store fp32 partials ----
    float* dst = g_h2p + (size_t)ksb * TOKENS * 64;
#pragma unroll
    for (int ni = 0; ni < 8; ni++) {
        const int col = ni * 8 + tg * 2;
        float2 p01 = unpack2(acc2[ni][0]);
        float2 p23 = unpack2(acc2[ni][1]);
        *reinterpret_cast<float2*>(&dst[(size_t)row0 * 64 + col]) = p01;
        *reinterpret_cast<float2*>(&dst[(size_t)(row0 + 8) * 64 + col]) = p23;
    }
}

// ---------------------------------------------------------------------------
// kR: h2 = sum of 4 partials -> frag-ordered hi/lo uint4 arrays.
// ---------------------------------------------------------------------------
__global__ void __launch_bounds__(256) kR_reduce() {
    int idx = blockIdx.x * 256 + threadIdx.x;   // 65536 total
    int lane = idx & 31, tg = lane & 3, gid = (lane >> 2) & 7;
    int ks = (idx >> 5) & 3;
    int rt16 = idx >> 7;
    int row = rt16 * 16 + gid;
    int k0  = ks * 16 + tg * 2;

    float2 v[4];
#pragma unroll
    for (int j = 0; j < 4; j++) v[j] = make_float2(0.f, 0.f);
#pragma unroll
    for (int part = 0; part < KSPLIT; part++) {
        const float* base = g_h2p + (size_t)part * TOKENS * 64;
        const float2 a0 = *reinterpret_cast<const float2*>(base + (size_t)row * 64 + k0);
        const float2 a1 = *reinterpret_cast<const float2*>(base + (size_t)(row + 8) * 64 + k0);
        const float2 a2 = *reinterpret_cast<const float2*>(base + (size_t)row * 64 + k0 + 8);
        const float2 a3 = *reinterpret_cast<const float2*>(base + (size_t)(row + 8) * 64 + k0 + 8);
        v[0].x += a0.x; v[0].y += a0.y;
        v[1].x += a1.x; v[1].y += a1.y;
        v[2].x += a2.x; v[2].y += a2.y;
        v[3].x += a3.x; v[3].y += a3.y;
    }
    uint4 oh, ol;
    split_pack(v[0], oh.x, ol.x);
    split_pack(v[1], oh.y, ol.y);
    split_pack(v[2], oh.z, ol.z);
    split_pack(v[3], oh.w, ol.w);
    g_h2FH[idx] = oh;
    g_h2FL[idx] = ol;
}

// ---------------------------------------------------------------------------
// k2: out[t][m] = sum_k h2[t][k] * a_q[m][k] + bias[m]
// Warp tile 32tok x 32m. CTA 128 tok x 64 m, warps 4(M) x 2(N). Grid (64,64).
// ---------------------------------------------------------------------------
__global__ void __launch_bounds__(256, 2) k2_expand(
    const float* __restrict__ bias,
    float* __restrict__ out)
{
    const int t    = threadIdx.x;
    const int wid  = t >> 5, lane = t & 31;
    const int gid  = lane >> 2, tg = lane & 3;
    const int wm   = wid & 3, wn = wid >> 2;
    const int m0   = blockIdx.x * 64 + wn * 32;
    const int t0   = blockIdx.y * 128 + wm * 32;
    const int rtb  = blockIdx.y * 8 + wm * 2;    // 16-row group base
    const int c8b  = blockIdx.x * 8 + wn * 4;    // 8-col group base

    float acc[2][4][4];
#pragma unroll
    for (int mi = 0; mi < 2; mi++)
#pragma unroll
        for (int ni = 0; ni < 4; ni++)
#pragma unroll
            for (int c = 0; c < 4; c++) acc[mi][ni][c] = 0.0f;

#pragma unroll
    for (int ks = 0; ks < 4; ks++) {
        uint4 ah[2], al[2], wf[4];
#pragma unroll
        for (int mi = 0; mi < 2; mi++) {
            int ia = ((rtb + mi) * 4 + ks) * 32 + lane;
            ah[mi] = __ldg(&g_h2FH[ia]);
            al[mi] = __ldg(&g_h2FL[ia]);
        }
#pragma unroll
        for (int ni = 0; ni < 4; ni++) {
            int ib = ((c8b + ni) * 4 + ks) * 32 + lane;
            wf[ni] = __ldg(&g_AqF[ib]);
        }
#pragma unroll
        for (int ni = 0; ni < 4; ni++) {
#pragma unroll
            for (int mi = 0; mi < 2; mi++) {
                mma_bf16(acc[mi][ni], reinterpret_cast<uint32_t*>(&ah[mi]), wf[ni].x, wf[ni].y);
                mma_bf16(acc[mi][ni], reinterpret_cast<uint32_t*>(&al[mi]), wf[ni].x, wf[ni].y);
                mma_bf16(acc[mi][ni], reinterpret_cast<uint32_t*>(&ah[mi]), wf[ni].z, wf[ni].w);
            }
        }
    }

    // epilogue: + bias, float2 stores
#pragma unroll
    for (int ni = 0; ni < 4; ni++) {
        const int col = m0 + ni * 8 + tg * 2;
        float2 bv = __ldg(reinterpret_cast<const float2*>(bias + col));
#pragma unroll
        for (int mi = 0; mi < 2; mi++) {
            const int row = t0 + mi * 16 + gid;
            float2 o0 = make_float2(acc[mi][ni][0] + bv.x, acc[mi][ni][1] + bv.y);
            float2 o1 = make_float2(acc[mi][ni][2] + bv.x, acc[mi][ni][3] + bv.y);
            *reinterpret_cast<float2*>(out + (size_t)row * FEAT + col)       = o0;
            *reinterpret_cast<float2*>(out + (size_t)(row + 8) * FEAT + col) = o1;
        }
    }
}

extern "C" void kernel_launch(void* const* d_in, const int* in_sizes, int n_in,
                              void* d_out, int out_size) {
    const float* x      = (const float*)d_in[0];
    const float* smooth = (const float*)d_in[1];
    const float* a_q    = (const float*)d_in[2];
    const float* b_q    = (const float*)d_in[3];
    const float* c_q_t  = (const float*)d_in[4];
    const float* bias   = (const float*)d_in[5];
    float* out          = (float*)d_out;

    kPrep<<<512, 256>>>(b_q, c_q_t, a_q);
    k1_quant_mma<<<dim3(KSPLIT, 64), 256>>>(x, smooth);
    kR_reduce<<<256, 256>>>();
    k2_expand<<<dim3(64, 64), 256>>>(bias, out);
}